// round 1
// baseline (speedup 1.0000x reference)
#include <cuda_runtime.h>
#include <cstdint>

// Problem constants (from reference_code)
#define DD   14
#define KK   2
#define BB   512
#define FF   512
#define NT   512
#define NF   1024
#define CELLS (BB * FF)          // 262144 (b,f) cells
#define PIX   (DD * DD)          // 196 pixels per cell

// One thread per (b,f) cell.
// img[b,f,i,j] = bg[b,f] + sum_k  h/(2*pi*w^2) * exp(-((i-sx)^2 + (j-sy)^2)/(2 w^2))
// Separable: ex[k][i] (with prefactor folded) * ey[k][j].
__global__ __launch_bounds__(256) void gaussian_spot_kernel(
    const float* __restrict__ height,      // [K,B,F]
    const float* __restrict__ width,       // [K,B,F]
    const float* __restrict__ x,           // [K,B,F]
    const float* __restrict__ y,           // [K,B,F]
    const float* __restrict__ background,  // [B,F]
    const float* __restrict__ target_locs, // [NT,NF,2]
    const int*   __restrict__ n_idx,       // [B,1]
    const int*   __restrict__ f_arr,       // [F]
    float*       __restrict__ out)         // [1,B,F,D,D]
{
    int cell = blockIdx.x * blockDim.x + threadIdx.x;
    if (cell >= CELLS) return;
    int b = cell / FF;
    int f = cell - b * FF;

    int n  = n_idx[b];
    int fi = f_arr[f];
    const float* lp = target_locs + ((size_t)n * NF + (size_t)fi) * 2;
    float loc0 = lp[0];
    float loc1 = lp[1];
    float bg = background[cell];

    float ex[KK][DD];
    float ey[KK][DD];

#pragma unroll
    for (int k = 0; k < KK; k++) {
        int off = k * CELLS + cell;
        float hk = height[off];
        float wk = width[off];
        float xk = x[off];
        float yk = y[off];

        float w2    = wk * wk;
        float invw2 = __fdividef(1.0f, w2);
        float inv2  = 0.5f * invw2;                       // 1/(2 w^2)
        float pref  = hk * 0.15915494309189535f * invw2;  // h / (2*pi*w^2)

        float sx = loc0 + xk;  // i-axis center
        float sy = loc1 + yk;  // j-axis center

#pragma unroll
        for (int i = 0; i < DD; i++) {
            float dx = (float)i - sx;
            ex[k][i] = pref * __expf(-dx * dx * inv2);
            float dy = (float)i - sy;
            ey[k][i] = __expf(-dy * dy * inv2);
        }
    }

    // 196 floats = 49 float4 chunks, 784B per cell (16B aligned).
    float4* op = reinterpret_cast<float4*>(out + (size_t)cell * PIX);
#pragma unroll
    for (int c = 0; c < 49; c++) {
        float4 v;
#pragma unroll
        for (int e = 0; e < 4; e++) {
            int idx = c * 4 + e;
            int i = idx / DD;   // compile-time constants after unroll
            int j = idx - i * DD;
            float acc = fmaf(ex[1][i], ey[1][j], bg);
            acc       = fmaf(ex[0][i], ey[0][j], acc);
            reinterpret_cast<float*>(&v)[e] = acc;
        }
        op[c] = v;
    }
}

extern "C" void kernel_launch(void* const* d_in, const int* in_sizes, int n_in,
                              void* d_out, int out_size)
{
    const float* height      = (const float*)d_in[0];
    const float* width       = (const float*)d_in[1];
    const float* x           = (const float*)d_in[2];
    const float* y           = (const float*)d_in[3];
    const float* background  = (const float*)d_in[4];
    const float* target_locs = (const float*)d_in[5];
    const int*   n_idx       = (const int*)d_in[6];
    const int*   f_arr       = (const int*)d_in[7];
    float*       out         = (float*)d_out;

    const int threads = 256;
    const int blocks  = (CELLS + threads - 1) / threads;
    gaussian_spot_kernel<<<blocks, threads>>>(height, width, x, y, background,
                                              target_locs, n_idx, f_arr, out);
}

// round 2
// speedup vs baseline: 2.1576x; 2.1576x over previous
#include <cuda_runtime.h>
#include <cstdint>

// Problem constants (from reference_code)
#define DD    14
#define KK    2
#define BB    512
#define FF    512
#define NT    512
#define NF    1024
#define CELLS (BB * FF)          // 262144 (b,f) cells
#define PIX   (DD * DD)          // 196 pixels per cell
#define WARPS_PER_BLOCK 8

// One WARP per (b,f) cell. Lanes 0..27 build the separable tables
// ex[k][i] (prefactor folded) / ey[k][j] in shared memory, then all lanes
// emit pixel pairs with fully coalesced float2 stores.
//
// img[b,f,i,j] = bg[b,f] + sum_k h/(2*pi*w^2) * exp(-((i-sx)^2+(j-sy)^2)/(2 w^2))
__global__ __launch_bounds__(256) void gaussian_spot_kernel(
    const float* __restrict__ height,      // [K,B,F]
    const float* __restrict__ width,       // [K,B,F]
    const float* __restrict__ x,           // [K,B,F]
    const float* __restrict__ y,           // [K,B,F]
    const float* __restrict__ background,  // [B,F]
    const float* __restrict__ target_locs, // [NT,NF,2]
    const int*   __restrict__ n_idx,       // [B,1]
    const int*   __restrict__ f_arr,       // [F]
    float*       __restrict__ out)         // [1,B,F,D,D]
{
    const int warp = threadIdx.x >> 5;
    const int lane = threadIdx.x & 31;
    const int cell = blockIdx.x * WARPS_PER_BLOCK + warp;   // grid sized exactly

    const int b = cell >> 9;        // cell / FF
    const int f = cell & (FF - 1);  // cell % FF

    // tab[warp][axis][d] = {val_spot0, val_spot1}; axis 0 = ex (pref folded), 1 = ey
    __shared__ float2 tab[WARPS_PER_BLOCK][2][16];

    // ---- broadcast-friendly parameter loads (all lanes same address) ----
    const int   n  = n_idx[b];
    const int   fi = f_arr[f];
    const float* lp = target_locs + ((size_t)n * NF + (size_t)fi) * 2;
    const float loc0 = lp[0];
    const float loc1 = lp[1];
    const float bg   = background[cell];

    float sx[KK], sy[KK], inv2[KK], pref[KK];
#pragma unroll
    for (int k = 0; k < KK; k++) {
        const int off = k * CELLS + cell;
        const float hk = height[off];
        const float wk = width[off];
        const float xk = x[off];
        const float yk = y[off];
        const float w2    = wk * wk;
        const float invw2 = __fdividef(1.0f, w2);
        inv2[k] = 0.5f * invw2;                       // 1/(2 w^2)
        pref[k] = hk * 0.15915494309189535f * invw2;  // h / (2*pi*w^2)
        sx[k] = loc0 + xk;                            // i-axis center
        sy[k] = loc1 + yk;                            // j-axis center
    }

    // ---- lanes 0..27 compute the 2x14 table entries for both spots ----
    if (lane < 2 * DD) {
        const int  axis = (lane >= DD) ? 1 : 0;
        const int  d    = axis ? (lane - DD) : lane;
        const float df  = (float)d;
        float2 v;
#pragma unroll
        for (int k = 0; k < KK; k++) {
            const float c  = axis ? sy[k] : sx[k];
            const float dd = df - c;
            float e = __expf(-dd * dd * inv2[k]);
            if (!axis) e *= pref[k];   // fold h/(2*pi*w^2) into the x-axis table
            ((float*)&v)[k] = e;
        }
        tab[warp][axis][d] = v;
    }
    __syncwarp();

    // ---- 98 pixel-pairs per cell; lanes write contiguous float2 (coalesced) ----
    float* outp = out + (size_t)cell * PIX;
#pragma unroll
    for (int r = 0; r < 4; r++) {
        const int p = r * 32 + lane;
        if (p < PIX / 2) {
            const int i = p / 7;            // row (pairs never cross rows: 14 even)
            const int j = (p - i * 7) * 2;  // first col of the pair
            const float2 exv = tab[warp][0][i];
            const float2 ey0 = tab[warp][1][j];
            const float2 ey1 = tab[warp][1][j + 1];
            float v0 = fmaf(exv.x, ey0.x, bg);
            v0       = fmaf(exv.y, ey0.y, v0);
            float v1 = fmaf(exv.x, ey1.x, bg);
            v1       = fmaf(exv.y, ey1.y, v1);
            *reinterpret_cast<float2*>(outp + 2 * p) = make_float2(v0, v1);
        }
    }
}

extern "C" void kernel_launch(void* const* d_in, const int* in_sizes, int n_in,
                              void* d_out, int out_size)
{
    const float* height      = (const float*)d_in[0];
    const float* width       = (const float*)d_in[1];
    const float* x           = (const float*)d_in[2];
    const float* y           = (const float*)d_in[3];
    const float* background  = (const float*)d_in[4];
    const float* target_locs = (const float*)d_in[5];
    const int*   n_idx       = (const int*)d_in[6];
    const int*   f_arr       = (const int*)d_in[7];
    float*       out         = (float*)d_out;

    const int threads = 32 * WARPS_PER_BLOCK;           // 256
    const int blocks  = CELLS / WARPS_PER_BLOCK;        // 32768 (exact)
    gaussian_spot_kernel<<<blocks, threads>>>(height, width, x, y, background,
                                              target_locs, n_idx, f_arr, out);
}

// round 3
// speedup vs baseline: 3.4889x; 1.6170x over previous
#include <cuda_runtime.h>
#include <cstdint>

// Problem constants (from reference_code)
#define DD    14
#define KK    2
#define BB    512
#define FF    512
#define NT    512
#define NF    1024
#define CELLS (BB * FF)          // 262144 (b,f) cells
#define PIX   (DD * DD)          // 196 pixels per cell
#define CPB   32                 // cells per block
#define THREADS 256

__device__ __forceinline__ float ex2(float a) {
    float r;
    asm("ex2.approx.ftz.f32 %0, %1;" : "=f"(r) : "f"(a));
    return r;
}

// Block handles 32 consecutive (b,f) cells.
// Phase 1 (threads 0..63): thread (axis, cell) builds the 14-entry separable
//   table for both spots via an incremental recurrence in log2 space:
//   a(d) = lp2 - (d-c)^2 * s2,  s2 = log2e/(2 w^2),  lp2 = log2(h/(2 pi w^2))
//   (lp2 folded into the x-axis only). a has constant 2nd difference -> 2 FADD/step.
// Phase 2 (8 warps x 4 cells): coalesced float2 pixel stores,
//   v = ex[i] * ey[j] summed over spots, + background.
__global__ __launch_bounds__(THREADS) void gaussian_spot_kernel(
    const float* __restrict__ height,      // [K,B,F]
    const float* __restrict__ width,       // [K,B,F]
    const float* __restrict__ x,           // [K,B,F]
    const float* __restrict__ y,           // [K,B,F]
    const float* __restrict__ background,  // [B,F]
    const float* __restrict__ target_locs, // [NT,NF,2]
    const int*   __restrict__ n_idx,       // [B,1]
    const int*   __restrict__ f_arr,       // [F]
    float*       __restrict__ out)         // [1,B,F,D,D]
{
    // tab entry (cell, axis, d) at [cell*33 + axis*16 + d], value {spot0, spot1}.
    // Stride 33 float2 = odd # of 8B bank-pairs -> conflict-free phase-1 STS.
    __shared__ float2 tab[CPB * 33];
    __shared__ float  bgs[CPB];

    const int t = threadIdx.x;
    const int blockbase = blockIdx.x * CPB;

    // ---------------- Phase 1: build tables (threads 0..63) ----------------
    if (t < 2 * CPB) {
        const int lc   = t & (CPB - 1);
        const int axis = t >> 5;          // 0 = x/i-axis, 1 = y/j-axis
        const int cell = blockbase + lc;
        const int b = cell >> 9;          // / FF
        const int f = cell & (FF - 1);

        const int n  = n_idx[b];          // broadcast within block
        const int fi = f_arr[f];          // coalesced
        const float cloc = target_locs[((size_t)n * NF + (size_t)fi) * 2 + axis];
        if (axis == 0) bgs[lc] = background[cell];   // coalesced

        float a[KK], dl[KK], e2[KK];
#pragma unroll
        for (int k = 0; k < KK; k++) {
            const int off = k * CELLS + cell;        // coalesced loads
            const float h  = height[off];
            const float w  = width[off];
            const float sh = axis ? y[off] : x[off];
            const float c  = cloc + sh;              // spot center on this axis
            const float w2    = w * w;
            const float invw2 = __fdividef(1.0f, w2);
            const float s2    = 0.72134752044f * invw2;   // log2e / (2 w^2)
            // fold h/(2*pi*w^2) into the x-axis table only
            const float lp2 = axis ? 0.0f
                                   : __log2f(h * 0.15915494309f * invw2);
            a[k]  = fmaf(-c * c, s2, lp2);           // a(0)
            dl[k] = (c + c - 1.0f) * s2;             // a(1)-a(0)
            e2[k] = s2 + s2;                         // -(2nd difference)
        }

        float2* trow = tab + lc * 33 + axis * 16;
#pragma unroll
        for (int d = 0; d < DD; d++) {
            trow[d] = make_float2(ex2(a[0]), ex2(a[1]));
            a[0] += dl[0]; dl[0] -= e2[0];
            a[1] += dl[1]; dl[1] -= e2[1];
        }
    }
    __syncthreads();

    // ---------------- Phase 2: emit pixels (all 8 warps, 4 cells each) ------
    const int warp = t >> 5;
    const int lane = t & 31;

    // hoisted pair indices: pair p = r*32+lane -> row i = p/7, col j = 2*(p%7)
    int ir[4], jr[4];
#pragma unroll
    for (int r = 0; r < 4; r++) {
        const int p = r * 32 + lane;
        ir[r] = p / 7;
        jr[r] = (p - ir[r] * 7) * 2;
    }

#pragma unroll
    for (int cc = 0; cc < 4; cc++) {
        const int lc = warp * 4 + cc;
        const float bg = bgs[lc];
        const float2* cex = tab + lc * 33;       // ex[i] (prefactor folded)
        const float2* cey = cex + 16;            // ey[j]
        float2* outp = reinterpret_cast<float2*>(out + (size_t)(blockbase + lc) * PIX);
#pragma unroll
        for (int r = 0; r < 4; r++) {
            const int p = r * 32 + lane;
            if (p < PIX / 2) {
                const float2 exv = cex[ir[r]];
                const float2 ey0 = cey[jr[r]];
                const float2 ey1 = cey[jr[r] + 1];
                float v0 = fmaf(exv.y, ey0.y, bg);
                v0       = fmaf(exv.x, ey0.x, v0);
                float v1 = fmaf(exv.y, ey1.y, bg);
                v1       = fmaf(exv.x, ey1.x, v1);
                outp[p] = make_float2(v0, v1);
            }
        }
    }
}

extern "C" void kernel_launch(void* const* d_in, const int* in_sizes, int n_in,
                              void* d_out, int out_size)
{
    const float* height      = (const float*)d_in[0];
    const float* width       = (const float*)d_in[1];
    const float* x           = (const float*)d_in[2];
    const float* y           = (const float*)d_in[3];
    const float* background  = (const float*)d_in[4];
    const float* target_locs = (const float*)d_in[5];
    const int*   n_idx       = (const int*)d_in[6];
    const int*   f_arr       = (const int*)d_in[7];
    float*       out         = (float*)d_out;

    const int blocks = CELLS / CPB;   // 8192
    gaussian_spot_kernel<<<blocks, THREADS>>>(height, width, x, y, background,
                                              target_locs, n_idx, f_arr, out);
}